// round 15
// baseline (speedup 1.0000x reference)
#include <cuda_runtime.h>
#include <cuda_bf16.h>

__global__ __launch_bounds__(256) void rinter_area_best(
    const float4* __restrict__ pts,      // N rows * 4 float4 each (16 floats)
    const int* __restrict__ num_of_inter,
    float* __restrict__ out,
    int n)
{
    int i = blockIdx.x * blockDim.x + threadIdx.x;
    if (i >= n) return;

    int ntri = num_of_inter[i] - 2;   // triangles valid for t < ntri

    float sum = 0.0f;
    if (ntri >= 1) {
        const float4* row = pts + (size_t)i * 4;
        // Sector 0 (points 0..3) — always needed when any triangle exists.
        float4 a = row[0];
        float4 b = row[1];
        // Sector 1 (points 4..7) — only when ntri >= 3. This two-guard split
        // is exactly 32B-L2-sector-optimal: skips sector-1 request bandwidth
        // for ntri in {1,2} rows, and skips the whole 128B line when both
        // rows sharing it are empty (ntri < 1).
        float4 c = make_float4(0.f, 0.f, 0.f, 0.f);
        float4 d = make_float4(0.f, 0.f, 0.f, 0.f);
        if (ntri >= 3) {
            c = row[2];
            d = row[3];
        }

        float px[8] = {a.x, a.z, b.x, b.z, c.x, c.z, d.x, d.z};
        float py[8] = {a.y, a.w, b.y, b.w, c.y, c.w, d.y, d.w};

        #pragma unroll
        for (int t = 0; t < 6; t++) {
            float cross = (px[0] - px[2 + t]) * (py[1 + t] - py[2 + t])
                        - (py[0] - py[2 + t]) * (px[1 + t] - px[2 + t]);
            sum += (t < ntri) ? fabsf(cross) * 0.5f : 0.0f;
        }
    }
    // Streaming store: write-once output, evict-first.
    __stcs(out + i, sum);
}

extern "C" void kernel_launch(void* const* d_in, const int* in_sizes, int n_in,
                              void* d_out, int out_size) {
    const float4* pts = (const float4*)d_in[0];
    const int* num_of_inter = (const int*)d_in[1];
    float* out = (float*)d_out;
    int n = in_sizes[1];

    int threads = 256;
    int blocks = (n + threads - 1) / threads;
    rinter_area_best<<<blocks, threads>>>(pts, num_of_inter, out, n);
}

// round 16
// speedup vs baseline: 1.0316x; 1.0316x over previous
#include <cuda_runtime.h>
#include <cuda_bf16.h>

__global__ __launch_bounds__(256) void rinter_area_best(
    const float4* __restrict__ pts,      // N rows * 4 float4 each (16 floats)
    const int* __restrict__ num_of_inter,
    float* __restrict__ out,
    int n)
{
    int i = blockIdx.x * blockDim.x + threadIdx.x;
    if (i >= n) return;

    int ntri = num_of_inter[i] - 2;   // triangles valid for t < ntri

    float sum = 0.0f;
    if (ntri >= 1) {
        const float4* row = pts + (size_t)i * 4;
        // Sector 0 (points 0..3) — always needed when any triangle exists.
        float4 a = row[0];
        float4 b = row[1];
        // Sector 1 (points 4..7) — only when ntri >= 3. This two-guard split
        // is exactly 32B-L2-sector-optimal: skips sector-1 request bandwidth
        // for ntri in {1,2} rows, and skips the whole 128B line when both
        // rows sharing it are empty (ntri < 1).
        float4 c = make_float4(0.f, 0.f, 0.f, 0.f);
        float4 d = make_float4(0.f, 0.f, 0.f, 0.f);
        if (ntri >= 3) {
            c = row[2];
            d = row[3];
        }

        float px[8] = {a.x, a.z, b.x, b.z, c.x, c.z, d.x, d.z};
        float py[8] = {a.y, a.w, b.y, b.w, c.y, c.w, d.y, d.w};

        #pragma unroll
        for (int t = 0; t < 6; t++) {
            float cross = (px[0] - px[2 + t]) * (py[1 + t] - py[2 + t])
                        - (py[0] - py[2 + t]) * (px[1 + t] - px[2 + t]);
            sum += (t < ntri) ? fabsf(cross) * 0.5f : 0.0f;
        }
    }
    // Streaming store: write-once output, evict-first.
    __stcs(out + i, sum);
}

extern "C" void kernel_launch(void* const* d_in, const int* in_sizes, int n_in,
                              void* d_out, int out_size) {
    const float4* pts = (const float4*)d_in[0];
    const int* num_of_inter = (const int*)d_in[1];
    float* out = (float*)d_out;
    int n = in_sizes[1];

    int threads = 256;
    int blocks = (n + threads - 1) / threads;
    rinter_area_best<<<blocks, threads>>>(pts, num_of_inter, out, n);
}